// round 14
// baseline (speedup 1.0000x reference)
#include <cuda_runtime.h>
#include <cstdint>

// Correlation layer: out[b, di*21+dj, h, w] = (1/64) * sum_c f1[b,c,h,w] * f2pad[b,c,h+di,w+dj]
// B=4, C=64, H=W=128, MAX_DISP=10, KS=21 (441 displacements), fp32.
//
// Layout (per buffer, float offsets), all regions swizzled with
// T(byte o) = o ^ ((o>>3) & 0x30)  [XOR byte bits 4-5 with bits 7-8],
// applied to region-relative offsets. Region bases are 512B-multiples so
// per-thread swizzled offsets are compile/init-time constants.
//   [0, 2048)      f1A: [h][c] rows of 128 floats (512B rows, phase 0)
//   [2048, 4096)   f1B: f1A shifted by +1 float (same structure)
//   [4096, 9216)   c0 : [c][r] rows, row stride 160 floats, channel stride
//                  640 floats (2560B ≡ 0 mod 512 -> phase = r mod 4, and a
//                  thread only ever reads row r* = hl+dil -> constant phase)

#define B_      4
#define C_      64
#define H_      128
#define W_      128
#define KS_     21
#define PAD_    10

#define HB   2
#define DIB  3
#define CC   8
#define NCHUNK (C_ / CC)   // 8
#define NROW (HB + DIB - 1)  // 4

#define PWR       160                 // c0 row stride (floats)
#define C0_CSTR   (NROW * PWR)        // 640 floats = 2560 B (≡0 mod 512)
#define OFF_F1B_F 2048
#define OFF_C0_F  4096
#define C0_SIZE   (CC * C0_CSTR)      // 5120 floats
#define BUF_FLOATS (OFF_C0_F + C0_SIZE)  // 9216 floats = 36864 B (≡0 mod 512)
#define SMEM_BYTES (3 * BUF_FLOATS * 4)  // 110592 B per CTA (2 CTAs/SM)

#define NTHREADS 192   // 6 warps = 2 hl * 3 dil; lanes = 16 wg * 2 djp

// ---------------- cp.async helpers ----------------
__device__ __forceinline__ void cp_async16(void* smem_dst, const float* gsrc) {
    uint32_t s = (uint32_t)__cvta_generic_to_shared(smem_dst);
    asm volatile("cp.async.cg.shared.global [%0], [%1], 16;\n" :: "r"(s), "l"(gsrc));
}
__device__ __forceinline__ void cp_async8(void* smem_dst, const float* gsrc) {
    uint32_t s = (uint32_t)__cvta_generic_to_shared(smem_dst);
    asm volatile("cp.async.ca.shared.global [%0], [%1], 8;\n" :: "r"(s), "l"(gsrc));
}
__device__ __forceinline__ void cp_commit() {
    asm volatile("cp.async.commit_group;\n" ::: "memory");
}
template <int N>
__device__ __forceinline__ void cp_wait() {
    asm volatile("cp.async.wait_group %0;\n" :: "n"(N) : "memory");
}

// packed f32x2 fma
__device__ __forceinline__ unsigned long long fma_x2(unsigned long long a,
                                                     unsigned long long b,
                                                     unsigned long long c) {
    unsigned long long d;
    asm("fma.rn.f32x2 %0, %1, %2, %3;" : "=l"(d) : "l"(a), "l"(b), "l"(c));
    return d;
}

// byte-offset swizzle (region-relative)
__device__ __forceinline__ int sw_b(int o) { return o ^ ((o >> 3) & 0x30); }

// ---------------- inner compute ----------------
// Thread tile: w in [w0, w0+8), w0 = wg*8. acc[k][q]: packed pair
// (w0+2q, w0+2q+1) [+1 if djp] for dj = 2k - djp (k=0 junk when djp=1).
// fa: 2 LDS.128 from parity copy; fb: 7 LDS.128, window [w0, w0+28),
// parity-shared. Offsets are pre-swizzled per-thread constants.
__device__ __forceinline__ void compute_chunk(const char* f1p, const char* c0p,
                                              int faoff0, int faoff1,
                                              const int (&foff)[7],
                                              unsigned long long (&acc)[11][4]) {
#pragma unroll
    for (int c = 0; c < CC; c++) {
        ulonglong2 a0 = *reinterpret_cast<const ulonglong2*>(f1p + faoff0);
        ulonglong2 a1 = *reinterpret_cast<const ulonglong2*>(f1p + faoff1);
        unsigned long long fa2[4] = {a0.x, a0.y, a1.x, a1.y};
        unsigned long long fb2[14];
#pragma unroll
        for (int j = 0; j < 7; j++) {
            ulonglong2 t = *reinterpret_cast<const ulonglong2*>(c0p + foff[j]);
            fb2[2 * j] = t.x; fb2[2 * j + 1] = t.y;
        }
#pragma unroll
        for (int k = 0; k < 11; k++) {
#pragma unroll
            for (int q = 0; q < 4; q++)
                acc[k][q] = fma_x2(fa2[q], fb2[k + q], acc[k][q]);
        }
        f1p += 512;    // next c row of f1 (512B rows)
        c0p += 2560;   // next c block of c0 (phase-neutral: 2560 ≡ 0 mod 512)
    }
}

// ---------------- staging (cp.async, gmem -> swizzled smem) ----------------
__device__ __forceinline__ void stage_chunk(const float* __restrict__ f1base,
                                            const float* __restrict__ f2base,
                                            char* buf,
                                            int rlo, int nrows, int tid,
                                            int f1sw, int c0K) {
    // f1A: 512 16B blocks; idx = hc*32 + w4; dst byte = hc*512 + sw(w4*16)
    {
        const int w4 = tid & 31;            // invariant; f1sw = sw_b(w4*16)
        int hc = tid >> 5;                  // advances by 6
        const float* src0 = f1base + w4 * 4;
#pragma unroll
        for (int j = 0; j < 3; j++) {
            if (hc < HB * CC) {
                int h = hc >> 3, c = hc & 7;
                cp_async16(buf + hc * 512 + f1sw,
                           src0 + c * (H_ * W_) + h * W_);
            }
            hc += 6;
        }
    }
    // c0 interior x in [10,138) via 8B; items (r*8+c)*64 + x2.
    // dst byte (rel OFF_C0): c*2560 + sw(rr*640 + 40 + x2*8); c0K = 40 + x2*8.
    {
        int rc = tid >> 6;                  // advances by 3
        const int x2 = tid & 63;
        const int rcmax = nrows * 8;
        const float* src0 = f2base + rlo * W_ + x2 * 2;
        char* c0b = buf + OFF_C0_F * 4;
#pragma unroll
        for (int j = 0; j < 11; j++) {
            if (rc < rcmax) {
                int r = rc >> 3, c = rc & 7;
                int oin = (rlo + r) * 640 + c0K;
                cp_async8(c0b + c * 2560 + sw_b(oin),
                          src0 + c * (H_ * W_) + r * W_);
            }
            rc += 3;
        }
    }
}

// ---------------- f1B build (swizzled smem 1-float shift of f1A) ----------------
// logical f1B[x] = f1A[x+1]; per output block g reads logical blocks g, g+1.
__device__ __forceinline__ void build_f1b(char* buf, int tid) {
#pragma unroll
    for (int j = 0; j < 3; j++) {
        int g = tid + j * NTHREADS;
        if (g < 512) {
            int ta = (g ^ ((g >> 3) & 3)) << 4;
            int g1 = g + 1;
            int tb = (g1 ^ ((g1 >> 3) & 3)) << 4;  // g=511 -> garbage (masked lane only)
            float4 v = *reinterpret_cast<const float4*>(buf + ta);
            float nxt = *reinterpret_cast<const float*>(buf + tb);
            *reinterpret_cast<float4*>(buf + OFF_F1B_F * 4 + ta) =
                make_float4(v.y, v.z, v.w, nxt);
        }
    }
}

extern __shared__ float smem[];

__global__ __launch_bounds__(NTHREADS, 2)
void corr_kernel(const float* __restrict__ f1g,
                 const float* __restrict__ f2g,
                 float* __restrict__ out) {
    const int tid  = threadIdx.x;
    const int warp = tid >> 5;
    const int lane = tid & 31;
    const int hl   = warp & 1;
    const int dil  = warp >> 1;
    const int wg   = lane >> 1;
    const int djp  = lane & 1;
    const int w0   = wg * 8;
    const int rstar = hl + dil;          // this thread's c0 row (phase)

    // per-thread swizzled offset tables (bytes)
    int foff[7];
#pragma unroll
    for (int j = 0; j < 7; j++) {
        int ml = 2 * wg + j;
        int x  = ((ml >> 3) + rstar) & 3;
        foff[j] = (ml ^ x) << 4;
    }
    int faoff0, faoff1;
    {
        int m0 = 2 * wg;     faoff0 = (m0 ^ ((m0 >> 3) & 3)) << 4;
        int m1 = 2 * wg + 1; faoff1 = (m1 ^ ((m1 >> 3) & 3)) << 4;
    }
    const int f1sw = ((tid & 31) * 16) ^ ((((tid & 31) * 16) >> 3) & 0x30);
    const int c0K  = 40 + (tid & 63) * 8;
    int fixoff;   // swizzled within-c byte offset of c0 float (rstar*160 + 11 + 2wg)
    {
        int o = (rstar * PWR + 11 + 2 * wg) * 4;
        fixoff = sw_b(o);
    }

    const int b   = blockIdx.z;
    const int h0  = blockIdx.y * HB;
    const int di0 = blockIdx.x * DIB;
    const int r0  = h0 + di0 - PAD_;

    int rlo = (r0 < 0) ? -r0 : 0;
    int rhi = (r0 + NROW > H_) ? (H_ - r0) : NROW;
    if (rhi < rlo) { rlo = 0; rhi = 0; }
    const int nrows = rhi - rlo;

    char* bufA = reinterpret_cast<char*>(smem);
    char* bufB = bufA + BUF_FLOATS * 4;
    char* bufC = bufB + BUF_FLOATS * 4;

    // one-time zero of f1B + c0 regions in all three buffers
    {
        float4 z = make_float4(0.f, 0.f, 0.f, 0.f);
        const int n4 = (BUF_FLOATS - OFF_F1B_F) / 4;   // 1792 float4s
        float4* zA = reinterpret_cast<float4*>(bufA + OFF_F1B_F * 4);
        float4* zB = reinterpret_cast<float4*>(bufB + OFF_F1B_F * 4);
        float4* zC = reinterpret_cast<float4*>(bufC + OFF_F1B_F * 4);
        for (int i = tid; i < n4; i += NTHREADS) { zA[i] = z; zB[i] = z; zC[i] = z; }
    }
    __syncthreads();

    const float* f1base = f1g + ((size_t)b * C_ * H_ + h0) * W_;
    const float* f2base = f2g + ((size_t)b * C_ * H_ + r0) * W_;
    const int chunk_gstride = CC * H_ * W_;

    // prologue (round-12 schedule): stage 0,1; build f1B(0)
    stage_chunk(f1base, f2base, bufA, rlo, nrows, tid, f1sw, c0K);
    cp_commit();
    stage_chunk(f1base + chunk_gstride, f2base + chunk_gstride, bufB, rlo, nrows,
                tid, f1sw, c0K);
    cp_commit();
    cp_wait<1>();
    __syncthreads();
    build_f1b(bufA, tid);

    unsigned long long acc[11][4];
#pragma unroll
    for (int k = 0; k < 11; k++)
#pragma unroll
        for (int q = 0; q < 4; q++) acc[k][q] = 0ull;
    float accfix = 0.f;

    const int f1off = djp * (OFF_F1B_F * 4) + hl * (CC * 512);
    const int c0off = OFF_C0_F * 4 + rstar * (PWR * 4);
    const bool fixlane = (djp == 1) && (wg < 5);

    char* p0 = bufA;   // compute chunk cc
    char* p1 = bufB;   // build f1B for chunk cc+1
    char* p2 = bufC;   // stage chunk cc+2

    for (int cc = 0; cc < NCHUNK; cc++) {
        cp_wait<0>();          // drain S(cc+1) (only group in flight)
        __syncthreads();       // staging + f1B(cc) visible; p2's readers done

        if (cc + 2 < NCHUNK) {
            stage_chunk(f1base + (size_t)(cc + 2) * chunk_gstride,
                        f2base + (size_t)(cc + 2) * chunk_gstride,
                        p2, rlo, nrows, tid, f1sw, c0K);
            cp_commit();
        }
        if (cc + 1 < NCHUNK) build_f1b(p1, tid);

        compute_chunk(p0 + f1off, p0 + c0off, faoff0, faoff1, foff, acc);

        // fused fixup: w=0, dj=2t+11 needs sum_c f1[.,h,0] * c0row[2t+11]
        if (fixlane) {
            const char* fa0 = p0 + hl * (CC * 512);     // f1A row, float 0 (T=0)
            const char* fb0 = p0 + OFF_C0_F * 4 + fixoff;
#pragma unroll
            for (int c = 0; c < CC; c++)
                accfix = fmaf(*reinterpret_cast<const float*>(fa0 + c * 512),
                              *reinterpret_cast<const float*>(fb0 + c * 2560),
                              accfix);
        }

        char* t = p0; p0 = p1; p1 = p2; p2 = t;   // rotate
    }

    // ---- epilogue ----
    const float inv = 1.0f / 64.0f;
    const int di = di0 + dil;
    const int h  = h0 + hl;
    float* ob = out + (((size_t)b * (KS_ * KS_) + di * KS_) * H_ + h) * W_;

    if (djp == 0) {
        // dj = 2k, w = w0..w0+7 -> two aligned STG.128
        for (int k = 0; k < 11; k++) {
            float* o = ob + (size_t)(2 * k) * (H_ * W_) + w0;
            float2 a0 = *reinterpret_cast<float2*>(&acc[k][0]);
            float2 a1 = *reinterpret_cast<float2*>(&acc[k][1]);
            float2 a2 = *reinterpret_cast<float2*>(&acc[k][2]);
            float2 a3 = *reinterpret_cast<float2*>(&acc[k][3]);
            *reinterpret_cast<float4*>(o)     = make_float4(a0.x * inv, a0.y * inv,
                                                            a1.x * inv, a1.y * inv);
            *reinterpret_cast<float4*>(o + 4) = make_float4(a2.x * inv, a2.y * inv,
                                                            a3.x * inv, a3.y * inv);
        }
    } else {
        // dj = 2k-1 (k=1..10), w = w0+1..w0+8 (w=128 masked for wg==15)
        for (int k = 1; k < 11; k++) {
            float* o = ob + (size_t)(2 * k - 1) * (H_ * W_);
            float2 a0 = *reinterpret_cast<float2*>(&acc[k][0]);
            float2 a1 = *reinterpret_cast<float2*>(&acc[k][1]);
            float2 a2 = *reinterpret_cast<float2*>(&acc[k][2]);
            float2 a3 = *reinterpret_cast<float2*>(&acc[k][3]);
            o[w0 + 1] = a0.x * inv;
            *reinterpret_cast<float2*>(o + w0 + 2) = make_float2(a0.y * inv, a1.x * inv);
            *reinterpret_cast<float2*>(o + w0 + 4) = make_float2(a1.y * inv, a2.x * inv);
            *reinterpret_cast<float2*>(o + w0 + 6) = make_float2(a2.y * inv, a3.x * inv);
            if (wg < 15) o[w0 + 8] = a3.y * inv;
        }
        if (wg < 5) {
            // w=0, odd dj: dj=2wg+1 (<10) is padding-zero; dj=2wg+11 from accfix
            ob[(size_t)(2 * wg + 1) * (H_ * W_)] = 0.f;
            ob[(size_t)(2 * wg + 11) * (H_ * W_)] = accfix * inv;
        }
    }
}

extern "C" void kernel_launch(void* const* d_in, const int* in_sizes, int n_in,
                              void* d_out, int out_size) {
    const float* f1 = (const float*)d_in[0];
    const float* f2 = (const float*)d_in[1];
    float* out = (float*)d_out;

    cudaFuncSetAttribute(corr_kernel, cudaFuncAttributeMaxDynamicSharedMemorySize,
                         SMEM_BYTES);

    dim3 grid(KS_ / DIB, H_ / HB, B_);   // (7, 64, 4) = 1792 CTAs
    corr_kernel<<<grid, NTHREADS, SMEM_BYTES>>>(f1, f2, out);
}

// round 15
// speedup vs baseline: 1.0956x; 1.0956x over previous
#include <cuda_runtime.h>
#include <cstdint>

// Correlation layer: out[b, di*21+dj, h, w] = (1/64) * sum_c f1[b,c,h,w] * f2pad[b,c,h+di,w+dj]
// B=4, C=64, H=W=128, MAX_DISP=10, KS=21 (441 displacements), fp32.
//
// Even/odd 16B-block split layout (all offsets BYTES within one buffer):
//   f1A_E @ 0      (4096)   even blocks of f1A rows [h][c] (16 blocks/row packed)
//   f1A_O @ 4096   (4096)   odd blocks
//   f1B_E @ 8256   (4096)   f1B = f1A shifted +1 float; E/O split, 8256-0 ≡ 64 mod 128
//   f1B_O @ 12352  (4096)
//   c0_E  @ 16512  (10240)  c0 rows [c][r]: 20 E blocks/row (320B), c stride 1280B
//   c0_O  @ 26752  (10240)
// A thread's 28-float fb window = blocks 2wg..2wg+6 = E idx wg..wg+3 + O idx wg..wg+2
// -> 7 conflict-free LDS.128 with immediate offsets (vs 12 in the 2-piece scheme).

#define B_      4
#define C_      64
#define H_      128
#define W_      128
#define KS_     21
#define PAD_    10

#define HB   2
#define DIB  3
#define CC   8
#define NCHUNK (C_ / CC)   // 8
#define NROW (HB + DIB - 1)  // 4

#define OFF_F1AO  4096
#define OFF_F1B   8256      // ≡ 64 mod 128 vs f1A -> parity fa loads disjoint quads
#define OFF_C0    16512     // ≡ 0 mod 128
#define C0_EO     10240     // E->O region distance
#define C0_CSTR   1280      // per-channel stride (bytes) in each c0 region
#define C0_RSTR   320       // per-row stride (bytes)
#define BUF_BYTES 36992     // ≡ 0 mod 128
#define SMEM_BYTES (3 * BUF_BYTES)   // 110976 B per CTA (2 CTAs/SM)

#define NTHREADS 192   // 6 warps = 2 hl * 3 dil; lanes = 16 wg * 2 djp

// ---------------- cp.async helpers ----------------
__device__ __forceinline__ void cp_async16(void* smem_dst, const float* gsrc) {
    uint32_t s = (uint32_t)__cvta_generic_to_shared(smem_dst);
    asm volatile("cp.async.cg.shared.global [%0], [%1], 16;\n" :: "r"(s), "l"(gsrc));
}
__device__ __forceinline__ void cp_async8(void* smem_dst, const float* gsrc) {
    uint32_t s = (uint32_t)__cvta_generic_to_shared(smem_dst);
    asm volatile("cp.async.ca.shared.global [%0], [%1], 8;\n" :: "r"(s), "l"(gsrc));
}
__device__ __forceinline__ void cp_commit() {
    asm volatile("cp.async.commit_group;\n" ::: "memory");
}
template <int N>
__device__ __forceinline__ void cp_wait() {
    asm volatile("cp.async.wait_group %0;\n" :: "n"(N) : "memory");
}

// packed f32x2 fma
__device__ __forceinline__ unsigned long long fma_x2(unsigned long long a,
                                                     unsigned long long b,
                                                     unsigned long long c) {
    unsigned long long d;
    asm("fma.rn.f32x2 %0, %1, %2, %3;" : "=l"(d) : "l"(a), "l"(b), "l"(c));
    return d;
}

// ---------------- inner compute ----------------
// Thread: contiguous 8-float tile w in [w0, w0+8), w0 = 8wg.
// acc[k][q]: packed pair (w0+2q, w0+2q+1) [+1 if djp] for dj = 2k - djp.
// fa: blocks 2wg (E), 2wg+1 (O) of the parity copy -> fa2[0..3].
// fb: E idx wg+t (t=0..3) -> fb2[4t],fb2[4t+1]; O idx wg+t (t=0..2) ->
// fb2[4t+2],fb2[4t+3]. All immediate-offset conflict-free LDS.128.
__device__ __forceinline__ void compute_chunk(const char* fa_base,
                                              const char* fbE_base,
                                              unsigned long long (&acc)[11][4]) {
#pragma unroll
    for (int c = 0; c < CC; c++) {
        ulonglong2 aE = *reinterpret_cast<const ulonglong2*>(fa_base + c * 256);
        ulonglong2 aO = *reinterpret_cast<const ulonglong2*>(fa_base + OFF_F1AO + c * 256);
        unsigned long long fa2[4] = {aE.x, aE.y, aO.x, aO.y};
        unsigned long long fb2[14];
#pragma unroll
        for (int t = 0; t < 4; t++) {
            ulonglong2 v = *reinterpret_cast<const ulonglong2*>(
                fbE_base + c * C0_CSTR + t * 16);
            fb2[4 * t] = v.x; fb2[4 * t + 1] = v.y;
        }
#pragma unroll
        for (int t = 0; t < 3; t++) {
            ulonglong2 v = *reinterpret_cast<const ulonglong2*>(
                fbE_base + C0_EO + c * C0_CSTR + t * 16);
            fb2[4 * t + 2] = v.x; fb2[4 * t + 3] = v.y;
        }
#pragma unroll
        for (int k = 0; k < 11; k++) {
#pragma unroll
            for (int q = 0; q < 4; q++)
                acc[k][q] = fma_x2(fa2[q], fb2[k + q], acc[k][q]);
        }
    }
}

// ---------------- staging (cp.async, gmem -> split smem) ----------------
__device__ __forceinline__ void stage_chunk(const float* __restrict__ f1base,
                                            const float* __restrict__ f2base,
                                            char* buf,
                                            int rlo, int nrows, int tid,
                                            int K1, int K0) {
    // f1A: 512 16B blocks; block m = w4 within row hc = h*8+c.
    // K1 = (w4&1)*4096 + (w4>>1)*16  (per-thread constant)
    {
        const int w4 = tid & 31;
        int hc = tid >> 5;                  // advances by 6
        const float* src0 = f1base + w4 * 4;
#pragma unroll
        for (int j = 0; j < 3; j++) {
            if (hc < HB * CC) {
                int h = hc >> 3, c = hc & 7;
                cp_async16(buf + hc * 256 + K1,
                           src0 + c * (H_ * W_) + h * W_);
            }
            hc += 6;
        }
    }
    // c0 interior y = 10 + 2*x2 (8B pieces); block m = y>>2.
    // K0 = (m&1)*C0_EO + (m>>1)*16 + (y&3)*4  (per-thread constant)
    {
        int rc = tid >> 6;                  // advances by 3
        const int x2 = tid & 63;
        const int rcmax = nrows * 8;
        const float* src0 = f2base + rlo * W_ + x2 * 2;
        char* c0b = buf + OFF_C0 + rlo * C0_RSTR;
#pragma unroll
        for (int j = 0; j < 11; j++) {
            if (rc < rcmax) {
                int r = rc >> 3, c = rc & 7;
                cp_async8(c0b + c * C0_CSTR + r * C0_RSTR + K0,
                          src0 + c * (H_ * W_) + r * W_);
            }
            rc += 3;
        }
    }
}

// ---------------- f1B build (split-layout 1-float shift of f1A) ----------------
// output block g: floats 4g..4g+3 <- f1A floats 4g+1..4g+4.
// addrA(g) = (g&1)*4096 + (g>>1)*16. g=511's tail read is garbage consumed
// only by discarded (masked) epilogue halves.
__device__ __forceinline__ void build_f1b(char* buf, int tid) {
#pragma unroll
    for (int j = 0; j < 3; j++) {
        int g = tid + j * NTHREADS;
        if (g < 512) {
            int aA = ((g & 1) << 12) + ((g >> 1) << 4);
            int g1 = g + 1;
            int aB = ((g1 & 1) << 12) + ((g1 >> 1) << 4);
            float4 v = *reinterpret_cast<const float4*>(buf + aA);
            float nxt = *reinterpret_cast<const float*>(buf + aB);
            *reinterpret_cast<float4*>(buf + OFF_F1B + aA) =
                make_float4(v.y, v.z, v.w, nxt);
        }
    }
}

extern __shared__ float smem[];

__global__ __launch_bounds__(NTHREADS, 2)
void corr_kernel(const float* __restrict__ f1g,
                 const float* __restrict__ f2g,
                 float* __restrict__ out) {
    const int tid  = threadIdx.x;
    const int warp = tid >> 5;
    const int lane = tid & 31;
    const int hl   = warp & 1;
    const int dil  = warp >> 1;
    const int wg   = lane >> 1;
    const int djp  = lane & 1;
    const int w0   = wg * 8;
    const int rstar = hl + dil;          // this thread's c0 row

    // per-thread constant staging offsets
    const int w4 = tid & 31;
    const int K1 = ((w4 & 1) << 12) + ((w4 >> 1) << 4);
    const int yc = 10 + (tid & 63) * 2;
    const int mc = yc >> 2;
    const int K0 = (mc & 1) * C0_EO + ((mc >> 1) << 4) + ((yc & 3) << 2);
    // fixup offset: c0 float y = 11 + 2wg (odd), row rstar
    const int yf = 11 + 2 * wg;
    const int mf = yf >> 2;
    const int Kf = (mf & 1) * C0_EO + ((mf >> 1) << 4) + ((yf & 3) << 2);

    const int b   = blockIdx.z;
    const int h0  = blockIdx.y * HB;
    const int di0 = blockIdx.x * DIB;
    const int r0  = h0 + di0 - PAD_;

    int rlo = (r0 < 0) ? -r0 : 0;
    int rhi = (r0 + NROW > H_) ? (H_ - r0) : NROW;
    if (rhi < rlo) { rlo = 0; rhi = 0; }
    const int nrows = rhi - rlo;

    char* bufA = reinterpret_cast<char*>(smem);
    char* bufB = bufA + BUF_BYTES;
    char* bufC = bufB + BUF_BYTES;

    // one-time zero of f1B + c0 regions in all three buffers
    {
        float4 z = make_float4(0.f, 0.f, 0.f, 0.f);
        const int n4 = (BUF_BYTES - OFF_F1B) / 16;   // 1796
        for (int i = tid; i < n4; i += NTHREADS) {
            *reinterpret_cast<float4*>(bufA + OFF_F1B + i * 16) = z;
            *reinterpret_cast<float4*>(bufB + OFF_F1B + i * 16) = z;
            *reinterpret_cast<float4*>(bufC + OFF_F1B + i * 16) = z;
        }
    }
    __syncthreads();

    const float* f1base = f1g + ((size_t)b * C_ * H_ + h0) * W_;
    const float* f2base = f2g + ((size_t)b * C_ * H_ + r0) * W_;
    const int chunk_gstride = CC * H_ * W_;

    // prologue (round-12 schedule): stage 0,1; build f1B(0)
    stage_chunk(f1base, f2base, bufA, rlo, nrows, tid, K1, K0);
    cp_commit();
    stage_chunk(f1base + chunk_gstride, f2base + chunk_gstride, bufB, rlo, nrows,
                tid, K1, K0);
    cp_commit();
    cp_wait<1>();
    __syncthreads();
    build_f1b(bufA, tid);

    unsigned long long acc[11][4];
#pragma unroll
    for (int k = 0; k < 11; k++)
#pragma unroll
        for (int q = 0; q < 4; q++) acc[k][q] = 0ull;
    float accfix = 0.f;

    const int faoff  = djp * OFF_F1B + hl * 2048 + wg * 16;
    const int fbEoff = OFF_C0 + rstar * C0_RSTR + wg * 16;
    const bool fixlane = (djp == 1) && (wg < 5);

    char* p0 = bufA;   // compute chunk cc
    char* p1 = bufB;   // build f1B for chunk cc+1
    char* p2 = bufC;   // stage chunk cc+2

    for (int cc = 0; cc < NCHUNK; cc++) {
        cp_wait<0>();          // drain S(cc+1) (only group in flight)
        __syncthreads();       // staging + f1B(cc) visible; p2's readers done

        if (cc + 2 < NCHUNK) {
            stage_chunk(f1base + (size_t)(cc + 2) * chunk_gstride,
                        f2base + (size_t)(cc + 2) * chunk_gstride,
                        p2, rlo, nrows, tid, K1, K0);
            cp_commit();
        }
        if (cc + 1 < NCHUNK) build_f1b(p1, tid);

        compute_chunk(p0 + faoff, p0 + fbEoff, acc);

        // fused fixup: w=0, dj=2t+11 needs sum_c f1[.,h,0] * c0row[2t+11]
        if (fixlane) {
            const char* fa0 = p0 + hl * 2048;            // f1A row, float 0 (block 0 E)
            const char* fb0 = p0 + OFF_C0 + rstar * C0_RSTR + Kf;
#pragma unroll
            for (int c = 0; c < CC; c++)
                accfix = fmaf(*reinterpret_cast<const float*>(fa0 + c * 256),
                              *reinterpret_cast<const float*>(fb0 + c * C0_CSTR),
                              accfix);
        }

        char* t = p0; p0 = p1; p1 = p2; p2 = t;   // rotate
    }

    // ---- epilogue ----
    const float inv = 1.0f / 64.0f;
    const int di = di0 + dil;
    const int h  = h0 + hl;
    float* ob = out + (((size_t)b * (KS_ * KS_) + di * KS_) * H_ + h) * W_;

    if (djp == 0) {
        // dj = 2k, w = w0..w0+7 -> two aligned STG.128
        for (int k = 0; k < 11; k++) {
            float* o = ob + (size_t)(2 * k) * (H_ * W_) + w0;
            float2 a0 = *reinterpret_cast<float2*>(&acc[k][0]);
            float2 a1 = *reinterpret_cast<float2*>(&acc[k][1]);
            float2 a2 = *reinterpret_cast<float2*>(&acc[k][2]);
            float2 a3 = *reinterpret_cast<float2*>(&acc[k][3]);
            *reinterpret_cast<float4*>(o)     = make_float4(a0.x * inv, a0.y * inv,
                                                            a1.x * inv, a1.y * inv);
            *reinterpret_cast<float4*>(o + 4) = make_float4(a2.x * inv, a2.y * inv,
                                                            a3.x * inv, a3.y * inv);
        }
    } else {
        // dj = 2k-1 (k=1..10), w = w0+1..w0+8 (w=128 masked for wg==15)
        for (int k = 1; k < 11; k++) {
            float* o = ob + (size_t)(2 * k - 1) * (H_ * W_);
            float2 a0 = *reinterpret_cast<float2*>(&acc[k][0]);
            float2 a1 = *reinterpret_cast<float2*>(&acc[k][1]);
            float2 a2 = *reinterpret_cast<float2*>(&acc[k][2]);
            float2 a3 = *reinterpret_cast<float2*>(&acc[k][3]);
            o[w0 + 1] = a0.x * inv;
            *reinterpret_cast<float2*>(o + w0 + 2) = make_float2(a0.y * inv, a1.x * inv);
            *reinterpret_cast<float2*>(o + w0 + 4) = make_float2(a1.y * inv, a2.x * inv);
            *reinterpret_cast<float2*>(o + w0 + 6) = make_float2(a2.y * inv, a3.x * inv);
            if (wg < 15) o[w0 + 8] = a3.y * inv;
        }
        if (wg < 5) {
            // w=0, odd dj: dj=2wg+1 (<10) is padding-zero; dj=2wg+11 from accfix
            ob[(size_t)(2 * wg + 1) * (H_ * W_)] = 0.f;
            ob[(size_t)(2 * wg + 11) * (H_ * W_)] = accfix * inv;
        }
    }
}

extern "C" void kernel_launch(void* const* d_in, const int* in_sizes, int n_in,
                              void* d_out, int out_size) {
    const float* f1 = (const float*)d_in[0];
    const float* f2 = (const float*)d_in[1];
    float* out = (float*)d_out;

    cudaFuncSetAttribute(corr_kernel, cudaFuncAttributeMaxDynamicSharedMemorySize,
                         SMEM_BYTES);

    dim3 grid(KS_ / DIB, H_ / HB, B_);   // (7, 64, 4) = 1792 CTAs
    corr_kernel<<<grid, NTHREADS, SMEM_BYTES>>>(f1, f2, out);
}

// round 16
// speedup vs baseline: 1.3140x; 1.1993x over previous
#include <cuda_runtime.h>
#include <cstdint>

// Correlation layer: out[b, di*21+dj, h, w] = (1/64) * sum_c f1[b,c,h,w] * f2pad[b,c,h+di,w+dj]
// B=4, C=64, H=W=128, MAX_DISP=10, KS=21 (441 displacements), fp32.
// R12 structure (best measured: 139.6us) + streaming output stores.

#define B_      4
#define C_      64
#define H_      128
#define W_      128
#define KS_     21
#define PAD_    10

#define HB   2
#define DIB  3
#define CC   8
#define NCHUNK (C_ / CC)   // 8
#define PW   152
#define NROW (HB + DIB - 1)  // 4

#define F2_STRIDE (CC * PW + 4)           // 1220 floats
#define F1A_SIZE  (HB * CC * W_)          // 2048 floats
#define OFF_F1B   (F1A_SIZE + 16)         // 2064: 8256 B ≡ 64 mod 128 -> parity
                                          // fa loads hit disjoint bank quads
#define F1B_SIZE  (F1A_SIZE + 4)          // 2052
#define OFF_C0    (OFF_F1B + F1B_SIZE)    // 4116 floats (16B-aligned)
#define F2_USED   (NROW * F2_STRIDE)      // 4880
#define BUF_FLOATS (OFF_C0 + F2_USED + 12) // 9008 floats = 36032 B
#define SMEM_BYTES (3 * BUF_FLOATS * 4)    // 108096 B per CTA (2 CTAs/SM)

#define NTHREADS 192   // 6 warps = 2 hl * 3 dil; lanes = 16 wg * 2 djp

// ---------------- cp.async helpers ----------------
__device__ __forceinline__ void cp_async16(float* smem_dst, const float* gsrc) {
    uint32_t s = (uint32_t)__cvta_generic_to_shared(smem_dst);
    asm volatile("cp.async.cg.shared.global [%0], [%1], 16;\n" :: "r"(s), "l"(gsrc));
}
__device__ __forceinline__ void cp_async8(float* smem_dst, const float* gsrc) {
    uint32_t s = (uint32_t)__cvta_generic_to_shared(smem_dst);
    asm volatile("cp.async.ca.shared.global [%0], [%1], 8;\n" :: "r"(s), "l"(gsrc));
}
__device__ __forceinline__ void cp_commit() {
    asm volatile("cp.async.commit_group;\n" ::: "memory");
}
template <int N>
__device__ __forceinline__ void cp_wait() {
    asm volatile("cp.async.wait_group %0;\n" :: "n"(N) : "memory");
}

// packed f32x2 fma
__device__ __forceinline__ unsigned long long fma_x2(unsigned long long a,
                                                     unsigned long long b,
                                                     unsigned long long c) {
    unsigned long long d;
    asm("fma.rn.f32x2 %0, %1, %2, %3;" : "=l"(d) : "l"(a), "l"(b), "l"(c));
    return d;
}

// streaming stores (evict-first; output is write-once)
__device__ __forceinline__ void stcs4(float* p, float4 v) {
    asm volatile("st.global.cs.v4.f32 [%0], {%1, %2, %3, %4};"
                 :: "l"(p), "f"(v.x), "f"(v.y), "f"(v.z), "f"(v.w) : "memory");
}
__device__ __forceinline__ void stcs2(float* p, float2 v) {
    asm volatile("st.global.cs.v2.f32 [%0], {%1, %2};"
                 :: "l"(p), "f"(v.x), "f"(v.y) : "memory");
}
__device__ __forceinline__ void stcs1(float* p, float v) {
    asm volatile("st.global.cs.f32 [%0], %1;" :: "l"(p), "f"(v) : "memory");
}

// ---------------- inner compute ----------------
// Identical instruction stream for both parities:
//   acc[k][2pc+p] += fa2[p] * fb2[k+p]
// djp=0: fa from f1A -> dj = 2k (k=0..10), w = pb+2p,+1
// djp=1: fa from shifted f1B -> dj = 2k-1 (k=0 junk), w = pb+2p+1,+2
// All LDS.128 lane address sets are conflict-free; fb is parity-shared.
__device__ __forceinline__ void compute_chunk(const float* __restrict__ f1p,
                                              const float* __restrict__ f2p,
                                              int pb0,
                                              unsigned long long (&acc)[11][4]) {
#pragma unroll
    for (int pc = 0; pc < 2; pc++) {
        const int pb = pb0 + pc * 64;
#pragma unroll
        for (int c = 0; c < CC; c++) {
            ulonglong2 fav = *reinterpret_cast<const ulonglong2*>(f1p + c * W_ + pb);
            unsigned long long fa2[2] = {fav.x, fav.y};
            const ulonglong2* fbv = reinterpret_cast<const ulonglong2*>(f2p + c * PW + pb);
            unsigned long long fb2[12];
#pragma unroll
            for (int i = 0; i < 6; i++) {
                ulonglong2 t = fbv[i];
                fb2[2 * i] = t.x; fb2[2 * i + 1] = t.y;
            }
#pragma unroll
            for (int k = 0; k < 11; k++) {
#pragma unroll
                for (int p = 0; p < 2; p++)
                    acc[k][2 * pc + p] = fma_x2(fa2[p], fb2[k + p], acc[k][2 * pc + p]);
            }
        }
    }
}

// ---------------- staging (cp.async, gmem -> smem) ----------------
__device__ __forceinline__ void stage_chunk(const float* __restrict__ f1base,
                                            const float* __restrict__ f2base,
                                            float* buf,
                                            int rlo, int nrows, int tid) {
    {
        const int w4 = tid & 31;
        int hc = tid >> 5;                  // advances by 6
        float* dst0 = buf + w4 * 4;
        const float* src0 = f1base + w4 * 4;
#pragma unroll
        for (int j = 0; j < 3; j++) {
            if (hc < HB * CC) {
                int h = hc >> 3, c = hc & 7;
                cp_async16(dst0 + hc * 256 + (h * F1A_SIZE / HB + c * W_ - hc * 256),
                           src0 + c * (H_ * W_) + h * W_);
            }
            hc += 6;
        }
    }
    {
        const int x2 = tid & 63;
        int rc = tid >> 6;                  // advances by 3
        const int rcmax = nrows * 8;
        float* c0 = buf + OFF_C0 + rlo * F2_STRIDE + PAD_ + x2 * 2;
        const float* src0 = f2base + rlo * W_ + x2 * 2;
#pragma unroll
        for (int j = 0; j < 11; j++) {
            if (rc < rcmax) {
                int r = rc >> 3, c = rc & 7;
                cp_async8(c0 + r * F2_STRIDE + c * PW,
                          src0 + c * (H_ * W_) + r * W_);
            }
            rc += 3;
        }
    }
}

// ---------------- f1B build (smem 1-float shift of f1A) ----------------
__device__ __forceinline__ void build_f1b(float* buf, int tid) {
    const float* a0 = buf;
    float* b0 = buf + OFF_F1B;
#pragma unroll
    for (int j = 0; j < 3; j++) {                 // ceil(512/192)
        int i4 = (tid + j * NTHREADS) * 4;
        if (i4 < F1A_SIZE) {
            float4 v = *reinterpret_cast<const float4*>(a0 + i4);
            float nxt = (i4 + 4 < F1A_SIZE) ? a0[i4 + 4] : 0.f;
            *reinterpret_cast<float4*>(b0 + i4) = make_float4(v.y, v.z, v.w, nxt);
        }
    }
}

extern __shared__ float smem[];

__global__ __launch_bounds__(NTHREADS, 2)
void corr_kernel(const float* __restrict__ f1g,
                 const float* __restrict__ f2g,
                 float* __restrict__ out) {
    const int tid  = threadIdx.x;
    const int warp = tid >> 5;
    const int lane = tid & 31;
    const int hl   = warp & 1;
    const int dil  = warp >> 1;
    const int wg   = lane >> 1;
    const int djp  = lane & 1;
    const int pb0  = wg * 4;

    const int b   = blockIdx.z;
    const int h0  = blockIdx.y * HB;
    const int di0 = blockIdx.x * DIB;
    const int r0  = h0 + di0 - PAD_;

    int rlo = (r0 < 0) ? -r0 : 0;
    int rhi = (r0 + NROW > H_) ? (H_ - r0) : NROW;
    if (rhi < rlo) { rlo = 0; rhi = 0; }
    const int nrows = rhi - rlo;

    float* bufA = smem;
    float* bufB = smem + BUF_FLOATS;
    float* bufC = smem + 2 * BUF_FLOATS;

    // one-time zero of f1B + c0 regions in all three buffers
    {
        float4 z = make_float4(0.f, 0.f, 0.f, 0.f);
        const int n4 = (BUF_FLOATS - OFF_F1B) / 4;
        float4* zA = reinterpret_cast<float4*>(bufA + OFF_F1B);
        float4* zB = reinterpret_cast<float4*>(bufB + OFF_F1B);
        float4* zC = reinterpret_cast<float4*>(bufC + OFF_F1B);
        for (int i = tid; i < n4; i += NTHREADS) { zA[i] = z; zB[i] = z; zC[i] = z; }
    }
    __syncthreads();

    const float* f1base = f1g + ((size_t)b * C_ * H_ + h0) * W_;
    const float* f2base = f2g + ((size_t)b * C_ * H_ + r0) * W_;
    const int chunk_gstride = CC * H_ * W_;

    // prologue: stage chunks 0,1; build f1B(0)
    stage_chunk(f1base, f2base, bufA, rlo, nrows, tid);
    cp_commit();
    stage_chunk(f1base + chunk_gstride, f2base + chunk_gstride, bufB, rlo, nrows, tid);
    cp_commit();
    cp_wait<1>();
    __syncthreads();
    build_f1b(bufA, tid);

    unsigned long long acc[11][4];
#pragma unroll
    for (int k = 0; k < 11; k++)
#pragma unroll
        for (int p = 0; p < 4; p++) acc[k][p] = 0ull;
    float accfix = 0.f;   // fused fixup accumulator (djp==1 && wg<5)

    const int f1off = djp * OFF_F1B + hl * (CC * W_);
    const int f2off = OFF_C0 + (hl + dil) * F2_STRIDE;
    const bool fixlane = (djp == 1) && (wg < 5);

    float* p0 = bufA;   // compute chunk cc
    float* p1 = bufB;   // build f1B for chunk cc+1
    float* p2 = bufC;   // stage chunk cc+2

    for (int cc = 0; cc < NCHUNK; cc++) {
        cp_wait<0>();          // drain S(cc+1) (only group in flight)
        __syncthreads();       // staging + f1B(cc) visible; p2's readers done

        if (cc + 2 < NCHUNK) {
            stage_chunk(f1base + (size_t)(cc + 2) * chunk_gstride,
                        f2base + (size_t)(cc + 2) * chunk_gstride,
                        p2, rlo, nrows, tid);
            cp_commit();
        }
        if (cc + 1 < NCHUNK) build_f1b(p1, tid);

        compute_chunk(p0 + f1off, p0 + f2off, pb0, acc);

        // fused fixup: out[b, di*21+(2t+11), h, 0] needs
        // sum_c f1[b,c,h,0] * c0row[2t+11]; zeroed OOB rows make the guard free.
        if (fixlane) {
            const float* fa0 = p0 + hl * (CC * W_);          // f1A (unshifted)
            const float* fb0 = p0 + f2off + 11 + 2 * wg;     // t = wg
#pragma unroll
            for (int c = 0; c < CC; c++)
                accfix = fmaf(fa0[c * W_], fb0[c * PW], accfix);
        }

        float* t = p0; p0 = p1; p1 = p2; p2 = t;   // rotate
    }

    // ---- epilogue (streaming stores) ----
    const float inv = 1.0f / 64.0f;
    const int di = di0 + dil;
    const int h  = h0 + hl;
    float* ob = out + (((size_t)b * (KS_ * KS_) + di * KS_) * H_ + h) * W_;

    if (djp == 0) {
        for (int k = 0; k < 11; k++) {
            float* o = ob + (size_t)(2 * k) * (H_ * W_);
#pragma unroll
            for (int pc = 0; pc < 2; pc++) {
                float2 f0 = *reinterpret_cast<float2*>(&acc[k][2 * pc]);
                float2 f1v = *reinterpret_cast<float2*>(&acc[k][2 * pc + 1]);
                stcs4(o + pb0 + pc * 64,
                      make_float4(f0.x * inv, f0.y * inv, f1v.x * inv, f1v.y * inv));
            }
        }
    } else {
        for (int k = 1; k < 11; k++) {
            float* o = ob + (size_t)(2 * k - 1) * (H_ * W_);
#pragma unroll
            for (int pc = 0; pc < 2; pc++) {
                const int pb = pb0 + pc * 64;
                float2 f0 = *reinterpret_cast<float2*>(&acc[k][2 * pc]);
                float2 f1v = *reinterpret_cast<float2*>(&acc[k][2 * pc + 1]);
                stcs1(o + pb + 1, f0.x * inv);
                stcs2(o + pb + 2, make_float2(f0.y * inv, f1v.x * inv));
                if (pb + 4 < W_) stcs1(o + pb + 4, f1v.y * inv);
            }
        }
        if (wg < 5) {
            // w=0, odd dj: dj=2wg+1 (<10) is padding-zero; dj=2wg+11 from accfix
            stcs1(ob + (size_t)(2 * wg + 1) * (H_ * W_), 0.f);
            stcs1(ob + (size_t)(2 * wg + 11) * (H_ * W_), accfix * inv);
        }
    }
}

extern "C" void kernel_launch(void* const* d_in, const int* in_sizes, int n_in,
                              void* d_out, int out_size) {
    const float* f1 = (const float*)d_in[0];
    const float* f2 = (const float*)d_in[1];
    float* out = (float*)d_out;

    cudaFuncSetAttribute(corr_kernel, cudaFuncAttributeMaxDynamicSharedMemorySize,
                         SMEM_BYTES);

    dim3 grid(KS_ / DIB, H_ / HB, B_);   // (7, 64, 4) = 1792 CTAs
    corr_kernel<<<grid, NTHREADS, SMEM_BYTES>>>(f1, f2, out);
}